// round 12
// baseline (speedup 1.0000x reference)
#include <cuda_runtime.h>
#include <cuda_bf16.h>

#define NPTS  1024
#define CAP   192
#define R2    (0.15f * 0.15f)

__device__ __forceinline__ unsigned long long ffma2(unsigned long long a,
                                                    unsigned long long b,
                                                    unsigned long long c) {
    unsigned long long d;
    asm("fma.rn.f32x2 %0, %1, %2, %3;" : "=l"(d) : "l"(a), "l"(b), "l"(c));
    return d;
}
__device__ __forceinline__ void unpack2(unsigned long long v, float& lo, float& hi) {
    asm("mov.b64 {%0, %1}, %2;" : "=f"(lo), "=f"(hi) : "l"(v));
}

__global__ __launch_bounds__(128, 7)
void pe_kernel(const float* __restrict__ x, const float* __restrict__ W1,
               const float* __restrict__ b1, const float* __restrict__ W2,
               const float* __restrict__ b2, float* __restrict__ out)
{
    __shared__ float sg[CAP * 3];                 // in-ball relative coords
    __shared__ float sd2[CAP];
    __shared__ float ssel[63 * 3];                // overflow-selected 63 nearest
    // per-warp double-buffered layer-1 tile: [warp][buf][local_rot*32 + ch]
    __shared__ __align__(16) float sh1[4][2][160];
    __shared__ float psum[4][32];                 // per-warp weighted rot-sums
    __shared__ int scnt, sselcnt;

    const int tid  = threadIdx.x;
    const int wrp  = tid >> 5;                    // 0..3
    const int c    = tid & 31;                    // lane = layer-1 channel
    const int rotg = wrp >> 1;                    // 0: rots 0-4, 1: rots 5-9
    const int half = wrp & 1;                     // output-channel half
    const int row  = c + 32 * half;               // this lane's W2 row
    const int b    = blockIdx.x >> 10;
    const int n    = blockIdx.x & (NPTS - 1);
    const float* xb = x + b * NPTS * 3;

    if (tid == 0) { scnt = 0; sselcnt = 0; }
    __syncthreads();

    const float qx = __ldg(&xb[n * 3 + 0]);
    const float qy = __ldg(&xb[n * 3 + 1]);
    const float qz = __ldg(&xb[n * 3 + 2]);

    // ---- ball query: 128 threads scan points from global (L1/L2 hit) ----
    for (int j = tid; j < NPTS; j += 128) {
        float dx = __ldg(&xb[j * 3 + 0]) - qx;
        float dy = __ldg(&xb[j * 3 + 1]) - qy;
        float dz = __ldg(&xb[j * 3 + 2]) - qz;
        float d2 = dx * dx + dy * dy + dz * dz;
        if (d2 <= R2 && j != n) {
            int p = atomicAdd(&scnt, 1);
            if (p < CAP) {
                sg[p * 3 + 0] = dx; sg[p * 3 + 1] = dy; sg[p * 3 + 2] = dz;
                sd2[p] = d2;
            }
        }
    }
    __syncthreads();

    int cnt = min(scnt, CAP);
    const float* glist = sg;
    int m = cnt;

    // Overflow (>63 others in ball): exact rank-select 63 nearest
    // (top_k parity; statistically unreachable for uniform points).
    if (cnt > 63) {
        for (int e = tid; e < cnt; e += 128) {
            float de = sd2[e];
            int rank = 0;
            for (int f = 0; f < cnt; ++f) {
                float df = sd2[f];
                rank += (df < de) || (df == de && f < e);
            }
            if (rank < 63) {
                int p = atomicAdd(&sselcnt, 1);
                ssel[p * 3 + 0] = sg[e * 3 + 0];
                ssel[p * 3 + 1] = sg[e * 3 + 1];
                ssel[p * 3 + 2] = sg[e * 3 + 2];
            }
        }
        __syncthreads();
        glist = ssel;
        m = 63;
    }

    // ---- per-lane layer-1 weights (lane = channel c, same for all warps) ----
    const float w1x = __ldg(&W1[c * 3 + 0]);
    const float w1y = __ldg(&W1[c * 3 + 1]);
    const float w1z = __ldg(&W1[c * 3 + 2]);
    const float b1c = __ldg(&b1[c]);

    // ---- ONE W2 row per lane (row = c + 32*half), channel-pair packed ----
    const unsigned long long* w2row =
        reinterpret_cast<const unsigned long long*>(W2 + row * 32);
    unsigned long long wpk[16];
    const float b2o = __ldg(&b2[row]);
    float self = 0.f;                      // bias-free response to gp = 0
    #pragma unroll
    for (int q = 0; q < 16; ++q) {
        wpk[q] = __ldg(&w2row[q]);
        float lo, hi; unpack2(wpk[q], lo, hi);
        self = fmaf(lo, fmaxf(__ldg(&b1[2 * q + 0]), 0.f), self);
        self = fmaf(hi, fmaxf(__ldg(&b1[2 * q + 1]), 0.f), self);
    }

    // Running bias-free pre-activation maxes for this warp's 5 rotations.
    float mv[5];
    #pragma unroll
    for (int r = 0; r < 5; ++r) mv[r] = self;

    float* buf0 = &sh1[wrp][0][0];
    float* buf1 = &sh1[wrp][1][0];

    // ---- main loop: each warp fully independent; __syncwarp only ----
    for (int k = 0; k < m; ++k) {
        float* buf = (k & 1) ? buf1 : buf0;
        const float gx = glist[k * 3 + 0];
        const float gy = glist[k * 3 + 1];
        const float gz = glist[k * 3 + 2];

        // layer 1 (redundant per warp, ~15 ops): this rot-group's 5 rots.
        float px = w1x * gx, py = w1y * gy, pz = w1z * gz;
        float h[5];
        if (rotg == 0) {           // full-sign rots 0-3 (w=1) + (+x axis, w=2)
            float a = b1c + px, d = b1c - px;
            float u = py + pz,  v = py - pz;
            h[0] = fmaxf(a + u, 0.f); h[1] = fmaxf(a - u, 0.f);
            h[2] = fmaxf(d + v, 0.f); h[3] = fmaxf(d - v, 0.f);
            h[4] = fmaxf(a, 0.f);
        } else {                   // (-x, +y, -y, +z, -z) axes, w=2 each
            h[0] = fmaxf(b1c - px, 0.f);
            h[1] = fmaxf(b1c + py, 0.f); h[2] = fmaxf(b1c - py, 0.f);
            h[3] = fmaxf(b1c + pz, 0.f); h[4] = fmaxf(b1c - pz, 0.f);
        }
        #pragma unroll
        for (int r = 0; r < 5; ++r) buf[r * 32 + c] = h[r];
        __syncwarp();

        // layer 2, q-outer: 5 accumulators cycle every 10 FFMA2 -> no RAW
        // stalls; next q's broadcast LDS.128 overlap this q's math.
        // Rot r = 32 floats = 8 ulonglong2 -> stride 8 (R10 bug: was 4).
        unsigned long long acc[5] = {0ull, 0ull, 0ull, 0ull, 0ull};
        const ulonglong2* hp = reinterpret_cast<const ulonglong2*>(buf);
        #pragma unroll
        for (int q = 0; q < 8; ++q) {
            #pragma unroll
            for (int r = 0; r < 5; ++r) {
                ulonglong2 hv = hp[r * 8 + q];   // rot r, channels 4q..4q+3
                acc[r] = ffma2(hv.x, wpk[2 * q + 0], acc[r]);
                acc[r] = ffma2(hv.y, wpk[2 * q + 1], acc[r]);
            }
        }
        #pragma unroll
        for (int r = 0; r < 5; ++r) {
            float lo, hi; unpack2(acc[r], lo, hi);
            mv[r] = fmaxf(mv[r], lo + hi);
        }
    }

    // ---- per-warp weighted rot-sums ----
    float pa = 0.f;
    #pragma unroll
    for (int r = 0; r < 5; ++r) {
        float wr = (rotg == 0 && r < 4) ? 1.f : 2.f;
        pa += wr * fmaxf(mv[r] + b2o, 0.f);
    }
    psum[wrp][c] = pa;
    __syncthreads();

    // threads 0-63 hold row == tid: combine both rot groups + 8 zero-diag c2.
    if (tid < 64) {
        const float c2 = fmaxf(self + b2o, 0.f);
        float fs = psum[half][c] + psum[2 + half][c] + 8.f * c2;
        out[(b * 64 + tid) * NPTS + n] = fs * (1.f / 24.f);
    }
}

extern "C" void kernel_launch(void* const* d_in, const int* in_sizes, int n_in,
                              void* d_out, int out_size)
{
    const float* x  = (const float*)d_in[0];  // [B,1024,3]
    const float* W1 = (const float*)d_in[1];  // [32,3]
    const float* b1 = (const float*)d_in[2];  // [32]
    const float* W2 = (const float*)d_in[3];  // [64,32]
    const float* b2 = (const float*)d_in[4];  // [64]
    float* out = (float*)d_out;               // [B,64,1024]

    int total_pts = in_sizes[0] / 3;          // B * 1024
    pe_kernel<<<total_pts, 128>>>(x, W1, b1, W2, b2, out);
}

// round 13
// speedup vs baseline: 1.0038x; 1.0038x over previous
#include <cuda_runtime.h>
#include <cuda_bf16.h>

#define NPTS  1024
#define CAP   192
#define R2    (0.15f * 0.15f)

// PWL table for the 6 single-axis rotations (+x,-x,+y,-y,+z,-z):
// A_o(t) = alpha[rot][seg][o] + beta[rot][seg][o] * t, seg = rank of t among
// the 32 breakpoints -b1[c]/e[c] (e = signed axis column of W1).
__device__ float2 g_tab[6 * 33 * 64];
__device__ float  g_sbp[6 * 32];       // sorted breakpoints per rot

__global__ void build_tab(const float* __restrict__ W1,
                          const float* __restrict__ b1,
                          const float* __restrict__ W2)
{
    const int rot  = blockIdx.x;           // 0..5
    const int axis = rot >> 1;
    const float sgn = (rot & 1) ? -1.f : 1.f;
    __shared__ float e[32], bb[32], sb[32];
    const int t = threadIdx.x;             // 64 threads; t = output row

    if (t < 32) {
        e[t]  = sgn * W1[t * 3 + axis];
        bb[t] = b1[t];
    }
    __syncthreads();
    if (t == 0) {
        float tmp[32];
        for (int c = 0; c < 32; ++c)
            tmp[c] = (e[c] != 0.f) ? (-bb[c] / e[c]) : 3.0e38f;
        for (int i = 1; i < 32; ++i) {      // insertion sort
            float v = tmp[i]; int j = i - 1;
            while (j >= 0 && tmp[j] > v) { tmp[j + 1] = tmp[j]; --j; }
            tmp[j + 1] = v;
        }
        for (int c = 0; c < 32; ++c) { sb[c] = tmp[c]; g_sbp[rot * 32 + c] = tmp[c]; }
    }
    __syncthreads();

    float w2r[32];
    #pragma unroll
    for (int c = 0; c < 32; ++c) w2r[c] = W2[t * 32 + c];

    for (int s = 0; s <= 32; ++s) {
        float lo = (s == 0)  ? -1.0e4f : sb[s - 1];
        float hi = (s == 32) ?  1.0e4f : sb[s];
        lo = fmaxf(lo, -1.0e4f); hi = fminf(hi, 1.0e4f);
        const float mid = 0.5f * (lo + hi);   // interior point of segment
        float alpha = 0.f, beta = 0.f;
        for (int c = 0; c < 32; ++c) {
            if (fmaf(e[c], mid, bb[c]) > 0.f) {   // relu active at mid
                alpha = fmaf(w2r[c], bb[c], alpha);
                beta  = fmaf(w2r[c], e[c],  beta);
            }
        }
        g_tab[(rot * 33 + s) * 64 + t] = make_float2(alpha, beta);
    }
}

__device__ __forceinline__ unsigned long long ffma2(unsigned long long a,
                                                    unsigned long long b,
                                                    unsigned long long c) {
    unsigned long long d;
    asm("fma.rn.f32x2 %0, %1, %2, %3;" : "=l"(d) : "l"(a), "l"(b), "l"(c));
    return d;
}
__device__ __forceinline__ void unpack2(unsigned long long v, float& lo, float& hi) {
    asm("mov.b64 {%0, %1}, %2;" : "=f"(lo), "=f"(hi) : "l"(v));
}

__global__ __launch_bounds__(64, 12)
void pe_kernel(const float* __restrict__ x, const float* __restrict__ W1,
               const float* __restrict__ b1, const float* __restrict__ W2,
               const float* __restrict__ b2, float* __restrict__ out)
{
    __shared__ float sg[CAP * 3];
    __shared__ float sd2[CAP];
    __shared__ float ssel[63 * 3];
    // per-warp double-buffered tile: 4 full-sign rots x 32 channels
    __shared__ __align__(16) float sh[2][2][128];
    __shared__ int scnt, sselcnt;

    const int tid  = threadIdx.x;
    const int wrp  = tid >> 5;
    const int c    = tid & 31;              // lane = layer-1 channel
    const int row  = c + 32 * wrp;          // this lane's output row
    const int b    = blockIdx.x >> 10;
    const int n    = blockIdx.x & (NPTS - 1);
    const float* xb = x + b * NPTS * 3;

    if (tid == 0) { scnt = 0; sselcnt = 0; }
    __syncthreads();

    const float qx = __ldg(&xb[n * 3 + 0]);
    const float qy = __ldg(&xb[n * 3 + 1]);
    const float qz = __ldg(&xb[n * 3 + 2]);

    // ---- ball query ----
    for (int j = tid; j < NPTS; j += 64) {
        float dx = __ldg(&xb[j * 3 + 0]) - qx;
        float dy = __ldg(&xb[j * 3 + 1]) - qy;
        float dz = __ldg(&xb[j * 3 + 2]) - qz;
        float d2 = dx * dx + dy * dy + dz * dz;
        if (d2 <= R2 && j != n) {
            int p = atomicAdd(&scnt, 1);
            if (p < CAP) {
                sg[p * 3 + 0] = dx; sg[p * 3 + 1] = dy; sg[p * 3 + 2] = dz;
                sd2[p] = d2;
            }
        }
    }
    __syncthreads();

    int cnt = min(scnt, CAP);
    const float* glist = sg;
    int m = cnt;

    // Overflow (>63 in ball): exact rank-select 63 nearest (top_k parity).
    if (cnt > 63) {
        for (int e = tid; e < cnt; e += 64) {
            float de = sd2[e];
            int rank = 0;
            for (int f = 0; f < cnt; ++f) {
                float df = sd2[f];
                rank += (df < de) || (df == de && f < e);
            }
            if (rank < 63) {
                int p = atomicAdd(&sselcnt, 1);
                ssel[p * 3 + 0] = sg[e * 3 + 0];
                ssel[p * 3 + 1] = sg[e * 3 + 1];
                ssel[p * 3 + 2] = sg[e * 3 + 2];
            }
        }
        __syncthreads();
        glist = ssel;
        m = 63;
    }

    // ---- per-lane layer-1 weights (channel = lane) ----
    const float w1x = __ldg(&W1[c * 3 + 0]);
    const float w1y = __ldg(&W1[c * 3 + 1]);
    const float w1z = __ldg(&W1[c * 3 + 2]);
    const float b1c = __ldg(&b1[c]);

    // ---- ONE W2 row per lane (row), channel-pair packed: 32 regs ----
    const unsigned long long* w2row =
        reinterpret_cast<const unsigned long long*>(W2 + row * 32);
    unsigned long long wpk[16];
    #pragma unroll
    for (int q = 0; q < 16; ++q) wpk[q] = __ldg(&w2row[q]);
    const float b2o = __ldg(&b2[row]);

    // breakpoints, one per lane per rot (rank via ballot needs no sorting,
    // but sorted values match the table's segment definition)
    float sbp[6];
    #pragma unroll
    for (int r = 0; r < 6; ++r) sbp[r] = g_sbp[r * 32 + c];

    // self = A(t=0) from rot 0's table (h(0) = relu(b1), rot-independent)
    float self;
    {
        unsigned mask = __ballot_sync(0xffffffffu, 0.f > sbp[0]);
        int seg = __popc(mask);
        self = g_tab[(0 * 33 + seg) * 64 + row].x;
    }

    float mvf[4], mva[6];
    #pragma unroll
    for (int r = 0; r < 4; ++r) mvf[r] = self;
    #pragma unroll
    for (int r = 0; r < 6; ++r) mva[r] = self;

    float* buf0 = &sh[wrp][0][0];
    float* buf1 = &sh[wrp][1][0];

    // ---- main loop: warps fully independent ----
    for (int k = 0; k < m; ++k) {
        float* buf = (k & 1) ? buf1 : buf0;
        const float gx = glist[k * 3 + 0];
        const float gy = glist[k * 3 + 1];
        const float gz = glist[k * 3 + 2];

        // 6 axis rotations via PWL table: ballot rank + coalesced LDG.64.
        // t is warp-uniform; lane holds one breakpoint; popc = segment.
        {
            const float ts[6] = {gx, gx, gy, gy, gz, gz};
            #pragma unroll
            for (int r = 0; r < 6; ++r) {
                unsigned mask = __ballot_sync(0xffffffffu, ts[r] > sbp[r]);
                int seg = __popc(mask);
                float2 ab = g_tab[(r * 33 + seg) * 64 + row];
                mva[r] = fmaxf(mva[r], fmaf(ab.y, ts[r], ab.x));
            }
        }

        // 4 full-sign rotations via smem tile (R=1).
        float px = w1x * gx, py = w1y * gy, pz = w1z * gz;
        float a = b1c + px, d = b1c - px;
        float u = py + pz,  v = py - pz;
        buf[0 * 32 + c] = fmaxf(a + u, 0.f);   // (+,+,+)
        buf[1 * 32 + c] = fmaxf(a - u, 0.f);   // (+,-,-)
        buf[2 * 32 + c] = fmaxf(d + v, 0.f);   // (-,+,-)
        buf[3 * 32 + c] = fmaxf(d - v, 0.f);   // (-,-,+)
        __syncwarp();

        unsigned long long acc[4] = {0ull, 0ull, 0ull, 0ull};
        const ulonglong2* hp = reinterpret_cast<const ulonglong2*>(buf);
        #pragma unroll
        for (int q = 0; q < 8; ++q) {
            #pragma unroll
            for (int r = 0; r < 4; ++r) {
                ulonglong2 hv = hp[r * 8 + q];    // rot r, channels 4q..4q+3
                acc[r] = ffma2(hv.x, wpk[2 * q + 0], acc[r]);
                acc[r] = ffma2(hv.y, wpk[2 * q + 1], acc[r]);
            }
        }
        #pragma unroll
        for (int r = 0; r < 4; ++r) {
            float lo, hi; unpack2(acc[r], lo, hi);
            mvf[r] = fmaxf(mvf[r], lo + hi);
        }
    }

    // mean over 24 rots: 4 full (w=1) + 6 axis (w=2) + 8 zero-diag (self)
    float fs = 8.f * fmaxf(self + b2o, 0.f);
    #pragma unroll
    for (int r = 0; r < 4; ++r) fs += fmaxf(mvf[r] + b2o, 0.f);
    #pragma unroll
    for (int r = 0; r < 6; ++r) fs += 2.f * fmaxf(mva[r] + b2o, 0.f);

    out[(b * 64 + row) * NPTS + n] = fs * (1.f / 24.f);
}

extern "C" void kernel_launch(void* const* d_in, const int* in_sizes, int n_in,
                              void* d_out, int out_size)
{
    const float* x  = (const float*)d_in[0];  // [B,1024,3]
    const float* W1 = (const float*)d_in[1];  // [32,3]
    const float* b1 = (const float*)d_in[2];  // [32]
    const float* W2 = (const float*)d_in[3];  // [64,32]
    const float* b2 = (const float*)d_in[4];  // [64]
    float* out = (float*)d_out;               // [B,64,1024]

    build_tab<<<6, 64>>>(W1, b1, W2);

    int total_pts = in_sizes[0] / 3;          // B * 1024
    pe_kernel<<<total_pts, 64>>>(x, W1, b1, W2, b2, out);
}